// round 3
// baseline (speedup 1.0000x reference)
#include <cuda_runtime.h>

#define D_DIM 128
#define T_TYPES 6
#define KDIM (T_TYPES * D_DIM + D_DIM)   // 896
#define LN_EPS 1e-5f
#define MAXN 50000

// Scratch (allocation-free rule: __device__ globals)
__device__ float g_sums[(size_t)MAXN * T_TYPES * D_DIM];   // (N,T,D) segment sums
__device__ int   g_cnt[MAXN * T_TYPES];                    // (N,T) segment counts
__device__ float g_inv[MAXN * T_TYPES];                    // 1/max(cnt,1)
__device__ float g_wrsum[D_DIM * D_DIM];                   // sum_t W_r[t]
__device__ float g_bias[D_DIM];                            // sum_t (b[t]+emb[t])

// ---------------------------------------------------------------------------
// Zero the scatter targets (must run every launch; graph replays).
// ---------------------------------------------------------------------------
__global__ void zero_kernel(int n_nodes) {
    size_t stride = (size_t)gridDim.x * blockDim.x;
    size_t base = (size_t)blockIdx.x * blockDim.x + threadIdx.x;
    size_t tot4 = (size_t)n_nodes * T_TYPES * D_DIM / 4;
    float4 z = make_float4(0.f, 0.f, 0.f, 0.f);
    for (size_t i = base; i < tot4; i += stride)
        reinterpret_cast<float4*>(g_sums)[i] = z;
    size_t nt = (size_t)n_nodes * T_TYPES;
    for (size_t i = base; i < nt; i += stride)
        g_cnt[i] = 0;
}

// ---------------------------------------------------------------------------
// Precompute sum_t W_r[t] and sum_t (b[t]+emb[t]).
// ---------------------------------------------------------------------------
__global__ void prep_kernel(const float* __restrict__ Wr,
                            const float* __restrict__ b,
                            const float* __restrict__ emb) {
    int i = blockIdx.x * blockDim.x + threadIdx.x;
    if (i < D_DIM * D_DIM) {
        float s = 0.f;
        #pragma unroll
        for (int t = 0; t < T_TYPES; t++) s += Wr[t * D_DIM * D_DIM + i];
        g_wrsum[i] = s;
    }
    if (i < D_DIM) {
        float s = 0.f;
        #pragma unroll
        for (int t = 0; t < T_TYPES; t++) s += b[t * D_DIM + i] + emb[t * D_DIM + i];
        g_bias[i] = s;
    }
}

// ---------------------------------------------------------------------------
// Edge scatter: one warp per edge. Gather x[src] (float4/lane) and
// atomically add into sums[(dst,type)]. float4 atomicAdd (sm_90+) -> RED.128.
// NOTE: edge_index / edge_type are int32 (JAX x64-disabled downcast).
// ---------------------------------------------------------------------------
__global__ __launch_bounds__(256) void scatter_kernel(
    const float* __restrict__ x,
    const int* __restrict__ ei,   // (2,E) int32
    const int* __restrict__ et,   // (E,)  int32
    int E)
{
    int w = (int)(((size_t)blockIdx.x * blockDim.x + threadIdx.x) >> 5);
    int lane = threadIdx.x & 31;
    if (w >= E) return;

    int src = ei[w];
    int dst = ei[E + w];
    int ty  = et[w];

    float4 xv = reinterpret_cast<const float4*>(x + (size_t)src * D_DIM)[lane];
    float4* dp = reinterpret_cast<float4*>(
        g_sums + ((size_t)dst * T_TYPES + (size_t)ty) * D_DIM) + lane;
    atomicAdd(dp, xv);
    if (lane == 0)
        atomicAdd(&g_cnt[dst * T_TYPES + ty], 1);
}

// ---------------------------------------------------------------------------
// inv = 1 / max(cnt, 1)
// ---------------------------------------------------------------------------
__global__ void inv_kernel(int nt) {
    int i = blockIdx.x * blockDim.x + threadIdx.x;
    if (i < nt)
        g_inv[i] = 1.f / fmaxf((float)g_cnt[i], 1.f);
}

// ---------------------------------------------------------------------------
// Fused GEMM + bias + LayerNorm + ReLU.
// A (N x 896): [mean_0..mean_5, x]  (mean = sums * inv, applied at tile load)
// B (896 x 128): [W_l[0..5]; Wr_sum]
// BM=64, BN=128, BK=32; 256 threads; per-thread 8x4 register tile.
// Epilogue: stage h tile in smem, per-row warp-shuffle LN + ReLU.
// ---------------------------------------------------------------------------
__global__ __launch_bounds__(256, 1) void gemm_ln_kernel(
    const float* __restrict__ x, const float* __restrict__ Wl,
    const float* __restrict__ gamma, const float* __restrict__ beta,
    float* __restrict__ out, int n_nodes)
{
    __shared__ float sm[64 * 128];       // 32 KB, reused: {As,Bs} then h
    float* As = sm;                      // [64][33] padded
    float* Bs = sm + 64 * 33;            // [32][128]

    const int tid  = threadIdx.x;
    const int rg   = tid >> 5;           // 0..7 : row group (8 rows each)
    const int lane = tid & 31;
    const int c0   = lane * 4;           // 4 consecutive output cols
    const int n0   = blockIdx.x * 64;

    float acc[8][4];
    #pragma unroll
    for (int i = 0; i < 8; i++)
        #pragma unroll
        for (int j = 0; j < 4; j++) acc[i][j] = 0.f;

    for (int kt = 0; kt < KDIM / 32; kt++) {
        const int k0 = kt * 32;
        // ---- load A tile: 64 rows x 32 k (512 float4, 2/thread) ----
        #pragma unroll
        for (int it = 0; it < 2; it++) {
            int m   = tid + it * 256;
            int row = m >> 3;
            int c4  = m & 7;
            int n   = n0 + row;
            float4 v = make_float4(0.f, 0.f, 0.f, 0.f);
            if (n < n_nodes) {
                if (k0 < T_TYPES * D_DIM) {
                    v = reinterpret_cast<const float4*>(
                            g_sums + (size_t)n * (T_TYPES * D_DIM) + k0)[c4];
                    float s = g_inv[n * T_TYPES + (k0 >> 7)];
                    v.x *= s; v.y *= s; v.z *= s; v.w *= s;
                } else {
                    v = reinterpret_cast<const float4*>(
                            x + (size_t)n * D_DIM + (k0 - T_TYPES * D_DIM))[c4];
                }
            }
            float* a = As + row * 33 + c4 * 4;
            a[0] = v.x; a[1] = v.y; a[2] = v.z; a[3] = v.w;
        }
        // ---- load B tile: 32 k x 128 cols (1024 float4, 4/thread) ----
        #pragma unroll
        for (int it = 0; it < 4; it++) {
            int m  = tid + it * 256;
            int kk = m >> 5;
            int c4 = m & 31;
            float4 v;
            if (k0 < T_TYPES * D_DIM)
                v = reinterpret_cast<const float4*>(
                        Wl + (size_t)(k0 + kk) * D_DIM)[c4];
            else
                v = reinterpret_cast<const float4*>(
                        g_wrsum + (size_t)(k0 - T_TYPES * D_DIM + kk) * D_DIM)[c4];
            reinterpret_cast<float4*>(Bs + kk * 128)[c4] = v;
        }
        __syncthreads();

        #pragma unroll
        for (int kk = 0; kk < 32; kk++) {
            float4 bv = reinterpret_cast<const float4*>(Bs + kk * 128 + c0)[0];
            #pragma unroll
            for (int i = 0; i < 8; i++) {
                float a = As[(rg * 8 + i) * 33 + kk];
                acc[i][0] += a * bv.x;
                acc[i][1] += a * bv.y;
                acc[i][2] += a * bv.z;
                acc[i][3] += a * bv.w;
            }
        }
        __syncthreads();
    }

    // ---- bias add, stage h tile in smem ----
    float4 bias = reinterpret_cast<const float4*>(g_bias + c0)[0];
    #pragma unroll
    for (int i = 0; i < 8; i++) {
        float4 v = make_float4(acc[i][0] + bias.x, acc[i][1] + bias.y,
                               acc[i][2] + bias.z, acc[i][3] + bias.w);
        reinterpret_cast<float4*>(sm + (rg * 8 + i) * 128 + c0)[0] = v;
    }
    __syncthreads();

    // ---- LayerNorm + ReLU: warp rg handles rows rg*8 .. rg*8+7 ----
    for (int rr = 0; rr < 8; rr++) {
        int r = rg * 8 + rr;
        int n = n0 + r;
        float v[4], s = 0.f, ss = 0.f;
        #pragma unroll
        for (int q = 0; q < 4; q++) {
            v[q] = sm[r * 128 + lane + q * 32];
            s  += v[q];
            ss += v[q] * v[q];
        }
        #pragma unroll
        for (int o = 16; o > 0; o >>= 1) {
            s  += __shfl_xor_sync(0xffffffffu, s,  o);
            ss += __shfl_xor_sync(0xffffffffu, ss, o);
        }
        float mean = s * (1.f / 128.f);
        float var  = ss * (1.f / 128.f) - mean * mean;
        float rstd = rsqrtf(var + LN_EPS);
        if (n < n_nodes) {
            #pragma unroll
            for (int q = 0; q < 4; q++) {
                int c = lane + q * 32;
                float y = (v[q] - mean) * rstd * gamma[c] + beta[c];
                out[(size_t)n * 128 + c] = fmaxf(y, 0.f);
            }
        }
    }
}

// ---------------------------------------------------------------------------
extern "C" void kernel_launch(void* const* d_in, const int* in_sizes, int n_in,
                              void* d_out, int out_size) {
    const float* x     = (const float*)d_in[0];
    const int*   ei    = (const int*)d_in[1];   // int32 (JAX x64 off)
    const int*   et    = (const int*)d_in[2];   // int32
    const float* Wl    = (const float*)d_in[3];
    const float* Wr    = (const float*)d_in[4];
    const float* b     = (const float*)d_in[5];
    const float* emb   = (const float*)d_in[6];
    const float* gamma = (const float*)d_in[7];
    const float* beta  = (const float*)d_in[8];
    float* out = (float*)d_out;

    int n_nodes = in_sizes[0] / D_DIM;
    int E       = in_sizes[2];

    zero_kernel<<<2048, 256>>>(n_nodes);
    prep_kernel<<<(D_DIM * D_DIM + 255) / 256, 256>>>(Wr, b, emb);
    scatter_kernel<<<(E + 7) / 8, 256>>>(x, ei, et, E);
    inv_kernel<<<(n_nodes * T_TYPES + 255) / 256, 256>>>(n_nodes * T_TYPES);
    gemm_ln_kernel<<<(n_nodes + 63) / 64, 256>>>(x, Wl, gamma, beta, out, n_nodes);
}